// round 3
// baseline (speedup 1.0000x reference)
#include <cuda_runtime.h>
#include <math.h>

// Problem constants (validated against in_sizes at launch)
#define NMAX 50000
#define EMAX 400000

// ---------------- scratch (device globals; no dynamic allocation) ----------------
__device__ float g_h1[(size_t)NMAX * 512];   // layer1 pre-softmax features
__device__ float g_o1[(size_t)NMAX * 512];   // layer1 output (post-elu)
__device__ float g_h2[(size_t)NMAX * 128];
__device__ float g_o2[(size_t)NMAX * 128];
__device__ float g_h3[NMAX * 8];
__device__ float g_o3[NMAX * 8];
__device__ float g_s[NMAX * 4];
__device__ float g_d[NMAX * 4];
__device__ int   g_counts[NMAX];
__device__ int   g_rowptr[NMAX + 1];
__device__ int   g_cursor[NMAX];
__device__ int   g_esrc[EMAX + NMAX];

// ---------------- CSR construction ----------------
__global__ void k_init_counts(int* counts, int nn) {
    int i = blockIdx.x * blockDim.x + threadIdx.x;
    if (i < nn) counts[i] = 1;   // self-loop per node
}

__global__ void k_count_edges(const int* __restrict__ ei, int* counts, int E) {
    int i = blockIdx.x * blockDim.x + threadIdx.x;
    if (i < E) atomicAdd(&counts[ei[E + i]], 1);   // dst = ei[1][i]
}

__global__ void k_scan(const int* __restrict__ counts, int* rp, int* cur, int nn) {
    __shared__ int part[1024];
    int tid = threadIdx.x;
    int per = (nn + 1023) >> 10;
    int b = tid * per;
    int e = min(b + per, nn);
    int s = 0;
    for (int i = b; i < e; i++) s += counts[i];
    part[tid] = s;
    __syncthreads();
    if (tid == 0) {
        int run = 0;
        for (int i = 0; i < 1024; i++) { int v = part[i]; part[i] = run; run += v; }
    }
    __syncthreads();
    int run = part[tid];
    for (int i = b; i < e; i++) { rp[i] = run; cur[i] = run; run += counts[i]; }
    if (e == nn) rp[nn] = run;   // total = E + nn (benign duplicate writes)
}

__global__ void k_scatter(const int* __restrict__ ei, int* cur, int* esrc, int E, int nn) {
    int i = blockIdx.x * blockDim.x + threadIdx.x;
    if (i >= E + nn) return;
    int s, dd;
    if (i < E) { s = ei[i]; dd = ei[E + i]; }
    else       { s = i - E; dd = s; }
    int pos = atomicAdd(&cur[dd], 1);
    esrc[pos] = s;
}

// ---------------- GEMM: C[M,N] = A[M,K] @ B[N,K]^T (both row-major) ----------------
__global__ void sgemm_nt(const float* __restrict__ A, const float* __restrict__ B,
                         float* __restrict__ C, int M, int N, int K) {
    __shared__ float As[8][64];
    __shared__ float Bs[8][65];
    int tid = threadIdx.x;
    int tx = tid & 15, ty = tid >> 4;
    int bm = blockIdx.y * 64, bn = blockIdx.x * 64;
    float acc[4][4] = {};
    for (int kk = 0; kk < K; kk += 8) {
#pragma unroll
        for (int i = 0; i < 2; i++) {
            int idx = tid + i * 256;
            int r = idx >> 3, k = idx & 7;
            float a = 0.f, b = 0.f;
            if (bm + r < M) a = A[(size_t)(bm + r) * K + kk + k];
            if (bn + r < N) b = B[(size_t)(bn + r) * K + kk + k];
            As[k][r] = a;
            Bs[k][r] = b;
        }
        __syncthreads();
#pragma unroll
        for (int k = 0; k < 8; k++) {
            float a[4], b[4];
#pragma unroll
            for (int i = 0; i < 4; i++) a[i] = As[k][ty * 4 + i];
#pragma unroll
            for (int j = 0; j < 4; j++) b[j] = Bs[k][tx * 4 + j];
#pragma unroll
            for (int i = 0; i < 4; i++)
#pragma unroll
                for (int j = 0; j < 4; j++) acc[i][j] += a[i] * b[j];
        }
        __syncthreads();
    }
#pragma unroll
    for (int i = 0; i < 4; i++) {
        int m = bm + ty * 4 + i;
        if (m >= M) continue;
#pragma unroll
        for (int j = 0; j < 4; j++) {
            int n = bn + tx * 4 + j;
            if (n < N) C[(size_t)m * N + n] = acc[i][j];
        }
    }
}

// ---------------- per-node attention logits s,d ----------------
template <int H, int C>
__global__ void k_sd(const float* __restrict__ h, const float* __restrict__ as,
                     const float* __restrict__ ad, float* __restrict__ s,
                     float* __restrict__ d, int nn) {
    int t = blockIdx.x * blockDim.x + threadIdx.x;
    if (t >= nn * H) return;
    int n = t / H, hh = t % H;
    const float* hp = h + (size_t)n * (H * C) + hh * C;
    float ss = 0.f, dd = 0.f;
#pragma unroll 4
    for (int c = 0; c < C; c++) {
        float v = hp[c];
        ss += v * as[hh * C + c];
        dd += v * ad[hh * C + c];
    }
    s[t] = ss;
    d[t] = dd;
}

// ---------------- GAT aggregation (atomic-free, CSR by dst) ----------------
// LPN lanes cooperate per node; VPL = H*C/LPN floats per lane; 8 lanes share a head.
template <int H, int C, int LPN>
__global__ void gat_agg(const float* __restrict__ h, const float* __restrict__ s,
                        const float* __restrict__ dv, const float* __restrict__ bias,
                        const int* __restrict__ rp, const int* __restrict__ esrc,
                        float* __restrict__ out, int nn) {
    constexpr int F = H * C;
    constexpr int VPL = F / LPN;
    constexpr int NPW = 32 / LPN;
    int gwarp = (blockIdx.x * blockDim.x + threadIdx.x) >> 5;
    int lane = threadIdx.x & 31;
    int node = gwarp * NPW + lane / LPN;
    if (node >= nn) return;
    int sub = lane % LPN;
    int myh = (sub * VPL) / C;
    float dval = dv[node * H + myh];
    int beg = rp[node], end = rp[node + 1];

    // pass 1: per-head max (8-lane subgroup covers all edges for one head)
    float m = -1e30f;
    for (int i = beg + (lane & 7); i < end; i += 8) {
        int sc = esrc[i];
        float e = s[sc * H + myh] + dval;
        e = e > 0.f ? e : 0.2f * e;
        m = fmaxf(m, e);
    }
    m = fmaxf(m, __shfl_xor_sync(0xffffffffu, m, 1));
    m = fmaxf(m, __shfl_xor_sync(0xffffffffu, m, 2));
    m = fmaxf(m, __shfl_xor_sync(0xffffffffu, m, 4));

    // pass 2: accumulate sum(w * h[src]) and sum(w)
    float acc[VPL];
#pragma unroll
    for (int j = 0; j < VPL; j++) acc[j] = 0.f;
    float den = 0.f;
    for (int i = beg; i < end; i++) {
        int sc = esrc[i];
        float e = s[sc * H + myh] + dval;
        e = e > 0.f ? e : 0.2f * e;
        float w = expf(e - m);
        den += w;
        if constexpr (VPL % 4 == 0) {
            const float4* hp4 = reinterpret_cast<const float4*>(h + (size_t)sc * F + sub * VPL);
#pragma unroll
            for (int j = 0; j < VPL / 4; j++) {
                float4 v = hp4[j];
                acc[4 * j + 0] += w * v.x;
                acc[4 * j + 1] += w * v.y;
                acc[4 * j + 2] += w * v.z;
                acc[4 * j + 3] += w * v.w;
            }
        } else {
            const float* hp = h + (size_t)sc * F + sub * VPL;
#pragma unroll
            for (int j = 0; j < VPL; j++) acc[j] += w * hp[j];
        }
    }
    float inv = 1.f / den;
#pragma unroll
    for (int j = 0; j < VPL; j++) {
        float v = acc[j] * inv + bias[sub * VPL + j];
        out[(size_t)node * F + sub * VPL + j] = v > 0.f ? v : expm1f(v);
    }
}

// ---------------- final edge MLP: 19 -> 16 -> 1 ----------------
__global__ void edge_mlp(const float* __restrict__ h3, const int* __restrict__ ei,
                         const float* __restrict__ ea, const float* __restrict__ yr,
                         const float* __restrict__ qt, const float* __restrict__ w1,
                         const float* __restrict__ b1, const float* __restrict__ w2,
                         const float* __restrict__ b2, float* __restrict__ out, int E) {
    __shared__ float sw1[16 * 19], sb1[16], sw2[16], sb2;
    for (int i = threadIdx.x; i < 16 * 19; i += blockDim.x) sw1[i] = w1[i];
    if (threadIdx.x < 16) { sb1[threadIdx.x] = b1[threadIdx.x]; sw2[threadIdx.x] = w2[threadIdx.x]; }
    if (threadIdx.x == 0) sb2 = b2[0];
    __syncthreads();
    int e = blockIdx.x * blockDim.x + threadIdx.x;
    if (e >= E) return;
    int si = ei[e], di = ei[E + e];
    float z[19];
#pragma unroll
    for (int j = 0; j < 8; j++) { z[j] = h3[si * 8 + j]; z[8 + j] = h3[di * 8 + j]; }
    z[16] = ea[e];
    z[17] = yr[e];
    z[18] = qt[e];
    float o = sb2;
#pragma unroll
    for (int j = 0; j < 16; j++) {
        float a = sb1[j];
#pragma unroll
        for (int i = 0; i < 19; i++) a += sw1[j * 19 + i] * z[i];
        o += sw2[j] * fmaxf(a, 0.f);
    }
    out[e] = o;
}

// ---------------- host ----------------
static void* sym_addr(const void* symbol) {
    void* p = nullptr;
    cudaGetSymbolAddress(&p, symbol);
    return p;
}

extern "C" void kernel_launch(void* const* d_in, const int* in_sizes, int n_in,
                              void* d_out, int out_size) {
    const float* x    = (const float*)d_in[0];
    const int*   ei   = (const int*)d_in[1];
    const float* ea   = (const float*)d_in[2];
    const float* yr   = (const float*)d_in[3];
    const float* qt   = (const float*)d_in[4];
    const float* W1   = (const float*)d_in[5];
    const float* a1s  = (const float*)d_in[6];
    const float* a1d  = (const float*)d_in[7];
    const float* b1   = (const float*)d_in[8];
    const float* W2   = (const float*)d_in[9];
    const float* a2s  = (const float*)d_in[10];
    const float* a2d  = (const float*)d_in[11];
    const float* b2   = (const float*)d_in[12];
    const float* W3   = (const float*)d_in[13];
    const float* a3s  = (const float*)d_in[14];
    const float* a3d  = (const float*)d_in[15];
    const float* b3   = (const float*)d_in[16];
    const float* f1w  = (const float*)d_in[17];
    const float* f1b  = (const float*)d_in[18];
    const float* f2w  = (const float*)d_in[19];
    const float* f2b  = (const float*)d_in[20];
    float* out = (float*)d_out;

    const int Nn = in_sizes[0] / 128;
    const int E  = in_sizes[1] / 2;

    float* h1 = (float*)sym_addr(g_h1);
    float* o1 = (float*)sym_addr(g_o1);
    float* h2 = (float*)sym_addr(g_h2);
    float* o2 = (float*)sym_addr(g_o2);
    float* h3 = (float*)sym_addr(g_h3);
    float* o3 = (float*)sym_addr(g_o3);
    float* sv = (float*)sym_addr(g_s);
    float* dv = (float*)sym_addr(g_d);
    int* counts = (int*)sym_addr(g_counts);
    int* rp     = (int*)sym_addr(g_rowptr);
    int* cur    = (int*)sym_addr(g_cursor);
    int* esrc   = (int*)sym_addr(g_esrc);

    const int TB = 128;

    // CSR (dst -> incoming src list), self-loops appended
    k_init_counts<<<(Nn + TB - 1) / TB, TB>>>(counts, Nn);
    k_count_edges<<<(E + TB - 1) / TB, TB>>>(ei, counts, E);
    k_scan<<<1, 1024>>>(counts, rp, cur, Nn);
    k_scatter<<<(E + Nn + TB - 1) / TB, TB>>>(ei, cur, esrc, E, Nn);

    // ---- layer 1: 128 -> 4x128 ----
    {
        dim3 g((512 + 63) / 64, (Nn + 63) / 64);
        sgemm_nt<<<g, 256>>>(x, W1, h1, Nn, 512, 128);
        k_sd<4, 128><<<(Nn * 4 + TB - 1) / TB, TB>>>(h1, a1s, a1d, sv, dv, Nn);
        gat_agg<4, 128, 32><<<(Nn * 32 + TB - 1) / TB, TB>>>(h1, sv, dv, b1, rp, esrc, o1, Nn);
    }
    // ---- layer 2: 512 -> 4x32 ----
    {
        dim3 g((128 + 63) / 64, (Nn + 63) / 64);
        sgemm_nt<<<g, 256>>>(o1, W2, h2, Nn, 128, 512);
        k_sd<4, 32><<<(Nn * 4 + TB - 1) / TB, TB>>>(h2, a2s, a2d, sv, dv, Nn);
        gat_agg<4, 32, 32><<<(Nn * 32 + TB - 1) / TB, TB>>>(h2, sv, dv, b2, rp, esrc, o2, Nn);
    }
    // ---- layer 3: 128 -> 1x8 ----
    {
        dim3 g((8 + 63) / 64, (Nn + 63) / 64);
        sgemm_nt<<<g, 256>>>(o2, W3, h3, Nn, 8, 128);
        k_sd<1, 8><<<(Nn + TB - 1) / TB, TB>>>(h3, a3s, a3d, sv, dv, Nn);
        gat_agg<1, 8, 8><<<(Nn * 8 + TB - 1) / TB, TB>>>(h3, sv, dv, b3, rp, esrc, o3, Nn);
    }
    // ---- edge MLP ----
    edge_mlp<<<(E + TB - 1) / TB, TB>>>(o3, ei, ea, yr, qt, f1w, f1b, f2w, f2b, out, E);
}

// round 5
// speedup vs baseline: 1.3911x; 1.3911x over previous
#include <cuda_runtime.h>
#include <math.h>

#define NMAX 50000
#define EMAX 400000

// ---------------- scratch (device globals; no dynamic allocation) ----------------
__device__ float g_h1[(size_t)NMAX * 512];
__device__ float g_o1[(size_t)NMAX * 512];
__device__ float g_h2[(size_t)NMAX * 128];
__device__ float g_o2[(size_t)NMAX * 128];
__device__ float g_h3[NMAX * 8];
__device__ float g_o3[NMAX * 8];
__device__ float g_s[NMAX * 4];
__device__ float g_d[NMAX * 4];
__device__ int   g_counts[NMAX];
__device__ int   g_rowptr[NMAX + 1];
__device__ int   g_cursor[NMAX];
__device__ int   g_esrc[EMAX + NMAX];

// ---------------- CSR construction ----------------
__global__ void k_init_counts(int* counts, int nn) {
    int i = blockIdx.x * blockDim.x + threadIdx.x;
    if (i < nn) counts[i] = 1;   // self-loop per node
}

__global__ void k_count_edges(const int* __restrict__ ei, int* counts, int E) {
    int i = blockIdx.x * blockDim.x + threadIdx.x;
    if (i < E) atomicAdd(&counts[ei[E + i]], 1);
}

__global__ void k_scan(const int* __restrict__ counts, int* rp, int* cur, int nn) {
    __shared__ int part[1024];
    int tid = threadIdx.x;
    int per = (nn + 1023) >> 10;
    int b = tid * per;
    int e = min(b + per, nn);
    int s = 0;
    for (int i = b; i < e; i++) s += counts[i];
    part[tid] = s;
    __syncthreads();
    if (tid == 0) {
        int run = 0;
        for (int i = 0; i < 1024; i++) { int v = part[i]; part[i] = run; run += v; }
    }
    __syncthreads();
    int run = part[tid];
    for (int i = b; i < e; i++) { rp[i] = run; cur[i] = run; run += counts[i]; }
    if (e == nn) rp[nn] = run;
}

__global__ void k_scatter(const int* __restrict__ ei, int* cur, int* esrc, int E, int nn) {
    int i = blockIdx.x * blockDim.x + threadIdx.x;
    if (i >= E + nn) return;
    int s, dd;
    if (i < E) { s = ei[i]; dd = ei[E + i]; }
    else       { s = i - E; dd = s; }
    int pos = atomicAdd(&cur[dd], 1);
    esrc[pos] = s;
}

// ---------------- big GEMM: C[M,N] = A[M,K] @ B[N,K]^T, 128x128 tile, 8x8/thread ----
// Requires: K % 16 == 0, N % 128 == 0 (true for layers 1 & 2). M arbitrary.
__global__ __launch_bounds__(256) void sgemm_nt_big(
    const float* __restrict__ A, const float* __restrict__ B,
    float* __restrict__ C, int M, int N, int K) {
    __shared__ float As[16][132];
    __shared__ float Bs[16][132];
    const int t = threadIdx.x;
    const int bm = blockIdx.y * 128, bn = blockIdx.x * 128;
    const int tx = t & 15, ty = t >> 4;
    const int r0 = t >> 2;            // 0..63
    const int c0 = (t & 3) * 4;       // 0,4,8,12

    float acc[8][8];
#pragma unroll
    for (int i = 0; i < 8; i++)
#pragma unroll
        for (int j = 0; j < 8; j++) acc[i][j] = 0.f;

    for (int kk = 0; kk < K; kk += 16) {
#pragma unroll
        for (int i = 0; i < 2; i++) {
            int r = r0 + i * 64;
            int gm = bm + r;
            float4 av = make_float4(0.f, 0.f, 0.f, 0.f);
            if (gm < M) av = *(const float4*)(A + (size_t)gm * K + kk + c0);
            As[c0 + 0][r] = av.x; As[c0 + 1][r] = av.y;
            As[c0 + 2][r] = av.z; As[c0 + 3][r] = av.w;
            int gn = bn + r;
            float4 bv = make_float4(0.f, 0.f, 0.f, 0.f);
            if (gn < N) bv = *(const float4*)(B + (size_t)gn * K + kk + c0);
            Bs[c0 + 0][r] = bv.x; Bs[c0 + 1][r] = bv.y;
            Bs[c0 + 2][r] = bv.z; Bs[c0 + 3][r] = bv.w;
        }
        __syncthreads();
#pragma unroll
        for (int k = 0; k < 16; k++) {
            float a[8], b[8];
            *(float4*)&a[0] = *(const float4*)&As[k][ty * 8];
            *(float4*)&a[4] = *(const float4*)&As[k][ty * 8 + 4];
            *(float4*)&b[0] = *(const float4*)&Bs[k][tx * 8];
            *(float4*)&b[4] = *(const float4*)&Bs[k][tx * 8 + 4];
#pragma unroll
            for (int i = 0; i < 8; i++)
#pragma unroll
                for (int j = 0; j < 8; j++) acc[i][j] += a[i] * b[j];
        }
        __syncthreads();
    }
#pragma unroll
    for (int i = 0; i < 8; i++) {
        int m = bm + ty * 8 + i;
        if (m >= M) continue;
        float* cp = C + (size_t)m * N + bn + tx * 8;
        *(float4*)cp = make_float4(acc[i][0], acc[i][1], acc[i][2], acc[i][3]);
        *(float4*)(cp + 4) = make_float4(acc[i][4], acc[i][5], acc[i][6], acc[i][7]);
    }
}

// ---------------- thin GEMM for layer 3: C[M,8] = A[M,128] @ W3[8,128]^T ----------
__global__ void gemm_thin8(const float* __restrict__ A, const float* __restrict__ B,
                           float* __restrict__ C, int M) {
    __shared__ float sB[8 * 128];
    for (int i = threadIdx.x; i < 8 * 128; i += blockDim.x) sB[i] = B[i];
    __syncthreads();
    int idx = blockIdx.x * blockDim.x + threadIdx.x;
    if (idx >= M * 8) return;
    int n = idx >> 3, j = idx & 7;
    const float* a = A + (size_t)n * 128;
    const float* w = sB + j * 128;
    float s = 0.f;
#pragma unroll
    for (int k = 0; k < 128; k += 4) {
        float4 v = *(const float4*)(a + k);
        s += v.x * w[k] + v.y * w[k + 1] + v.z * w[k + 2] + v.w * w[k + 3];
    }
    C[idx] = s;
}

// ---------------- per-node attention logits s,d: warp per (node,head) -------------
template <int H, int C>
__global__ void k_sd_w(const float* __restrict__ h, const float* __restrict__ as,
                       const float* __restrict__ ad, float* __restrict__ s,
                       float* __restrict__ d, int nn) {
    int w = (blockIdx.x * blockDim.x + threadIdx.x) >> 5;
    int lane = threadIdx.x & 31;
    if (w >= nn * H) return;
    int n = w / H, hh = w % H;
    float ss = 0.f, dd = 0.f;
    if (lane * 4 < C) {
        float4 v = *(const float4*)(h + (size_t)n * (H * C) + hh * C + lane * 4);
        float4 a = *(const float4*)(as + hh * C + lane * 4);
        float4 b = *(const float4*)(ad + hh * C + lane * 4);
        ss = v.x * a.x + v.y * a.y + v.z * a.z + v.w * a.w;
        dd = v.x * b.x + v.y * b.y + v.z * b.z + v.w * b.w;
    }
#pragma unroll
    for (int o = 16; o; o >>= 1) {
        ss += __shfl_xor_sync(0xffffffffu, ss, o);
        dd += __shfl_xor_sync(0xffffffffu, dd, o);
    }
    if (lane == 0) { s[w] = ss; d[w] = dd; }
}

// ---------------- GAT aggregation (atomic-free, CSR by dst) -----------------------
template <int H, int C, int LPN>
__global__ void gat_agg(const float* __restrict__ h, const float* __restrict__ s,
                        const float* __restrict__ dv, const float* __restrict__ bias,
                        const int* __restrict__ rp, const int* __restrict__ esrc,
                        float* __restrict__ out, int nn) {
    constexpr int F = H * C;
    constexpr int VPL = F / LPN;
    constexpr int NPW = 32 / LPN;
    int gwarp = (blockIdx.x * blockDim.x + threadIdx.x) >> 5;
    int lane = threadIdx.x & 31;
    int node = gwarp * NPW + lane / LPN;
    if (node >= nn) return;
    int sub = lane % LPN;
    int myh = (sub * VPL) / C;
    float dval = dv[node * H + myh];
    int beg = rp[node], end = rp[node + 1];

    // pass 1: per-head max
    float m = -1e30f;
    for (int i = beg + (lane & 7); i < end; i += 8) {
        int sc = esrc[i];
        float e = s[sc * H + myh] + dval;
        e = e > 0.f ? e : 0.2f * e;
        m = fmaxf(m, e);
    }
    m = fmaxf(m, __shfl_xor_sync(0xffffffffu, m, 1));
    m = fmaxf(m, __shfl_xor_sync(0xffffffffu, m, 2));
    m = fmaxf(m, __shfl_xor_sync(0xffffffffu, m, 4));

    // pass 2: accumulate
    float acc[VPL];
#pragma unroll
    for (int j = 0; j < VPL; j++) acc[j] = 0.f;
    float den = 0.f;
    for (int i = beg; i < end; i++) {
        int sc = esrc[i];
        float e = s[sc * H + myh] + dval;
        e = e > 0.f ? e : 0.2f * e;
        float w = __expf(e - m);
        den += w;
        if constexpr (VPL % 4 == 0) {
            const float4* hp4 = reinterpret_cast<const float4*>(h + (size_t)sc * F + sub * VPL);
#pragma unroll
            for (int j = 0; j < VPL / 4; j++) {
                float4 v = hp4[j];
                acc[4 * j + 0] += w * v.x;
                acc[4 * j + 1] += w * v.y;
                acc[4 * j + 2] += w * v.z;
                acc[4 * j + 3] += w * v.w;
            }
        } else {
            const float* hp = h + (size_t)sc * F + sub * VPL;
#pragma unroll
            for (int j = 0; j < VPL; j++) acc[j] += w * hp[j];
        }
    }
    float inv = 1.f / den;
#pragma unroll
    for (int j = 0; j < VPL; j++) {
        float v = acc[j] * inv + bias[sub * VPL + j];
        out[(size_t)node * F + sub * VPL + j] = v > 0.f ? v : expm1f(v);
    }
}

// ---------------- final edge MLP: 19 -> 16 -> 1 ----------------
__global__ void edge_mlp(const float* __restrict__ h3, const int* __restrict__ ei,
                         const float* __restrict__ ea, const float* __restrict__ yr,
                         const float* __restrict__ qt, const float* __restrict__ w1,
                         const float* __restrict__ b1, const float* __restrict__ w2,
                         const float* __restrict__ b2, float* __restrict__ out, int E) {
    __shared__ float sw1[16 * 19], sb1[16], sw2[16], sb2;
    for (int i = threadIdx.x; i < 16 * 19; i += blockDim.x) sw1[i] = w1[i];
    if (threadIdx.x < 16) { sb1[threadIdx.x] = b1[threadIdx.x]; sw2[threadIdx.x] = w2[threadIdx.x]; }
    if (threadIdx.x == 0) sb2 = b2[0];
    __syncthreads();
    int e = blockIdx.x * blockDim.x + threadIdx.x;
    if (e >= E) return;
    int si = ei[e], di = ei[E + e];
    float z[19];
#pragma unroll
    for (int j = 0; j < 8; j++) { z[j] = h3[si * 8 + j]; z[8 + j] = h3[di * 8 + j]; }
    z[16] = ea[e];
    z[17] = yr[e];
    z[18] = qt[e];
    float o = sb2;
#pragma unroll
    for (int j = 0; j < 16; j++) {
        float a = sb1[j];
#pragma unroll
        for (int i = 0; i < 19; i++) a += sw1[j * 19 + i] * z[i];
        o += sw2[j] * fmaxf(a, 0.f);
    }
    out[e] = o;
}

// ---------------- host ----------------
static void* sym_addr(const void* symbol) {
    void* p = nullptr;
    cudaGetSymbolAddress(&p, symbol);
    return p;
}

extern "C" void kernel_launch(void* const* d_in, const int* in_sizes, int n_in,
                              void* d_out, int out_size) {
    const float* x    = (const float*)d_in[0];
    const int*   ei   = (const int*)d_in[1];
    const float* ea   = (const float*)d_in[2];
    const float* yr   = (const float*)d_in[3];
    const float* qt   = (const float*)d_in[4];
    const float* W1   = (const float*)d_in[5];
    const float* a1s  = (const float*)d_in[6];
    const float* a1d  = (const float*)d_in[7];
    const float* b1   = (const float*)d_in[8];
    const float* W2   = (const float*)d_in[9];
    const float* a2s  = (const float*)d_in[10];
    const float* a2d  = (const float*)d_in[11];
    const float* b2   = (const float*)d_in[12];
    const float* W3   = (const float*)d_in[13];
    const float* a3s  = (const float*)d_in[14];
    const float* a3d  = (const float*)d_in[15];
    const float* b3   = (const float*)d_in[16];
    const float* f1w  = (const float*)d_in[17];
    const float* f1b  = (const float*)d_in[18];
    const float* f2w  = (const float*)d_in[19];
    const float* f2b  = (const float*)d_in[20];
    float* out = (float*)d_out;

    const int Nn = in_sizes[0] / 128;
    const int E  = in_sizes[1] / 2;

    float* h1 = (float*)sym_addr(g_h1);
    float* o1 = (float*)sym_addr(g_o1);
    float* h2 = (float*)sym_addr(g_h2);
    float* o2 = (float*)sym_addr(g_o2);
    float* h3 = (float*)sym_addr(g_h3);
    float* o3 = (float*)sym_addr(g_o3);
    float* sv = (float*)sym_addr(g_s);
    float* dv = (float*)sym_addr(g_d);
    int* counts = (int*)sym_addr(g_counts);
    int* rp     = (int*)sym_addr(g_rowptr);
    int* cur    = (int*)sym_addr(g_cursor);
    int* esrc   = (int*)sym_addr(g_esrc);

    const int TB = 128;

    // CSR (dst -> incoming src list), self-loops appended
    k_init_counts<<<(Nn + TB - 1) / TB, TB>>>(counts, Nn);
    k_count_edges<<<(E + TB - 1) / TB, TB>>>(ei, counts, E);
    k_scan<<<1, 1024>>>(counts, rp, cur, Nn);
    k_scatter<<<(E + Nn + TB - 1) / TB, TB>>>(ei, cur, esrc, E, Nn);

    // ---- layer 1: 128 -> 4x128 ----
    {
        dim3 g(512 / 128, (Nn + 127) / 128);
        sgemm_nt_big<<<g, 256>>>(x, W1, h1, Nn, 512, 128);
        k_sd_w<4, 128><<<(Nn * 4 * 32 + TB - 1) / TB, TB>>>(h1, a1s, a1d, sv, dv, Nn);
        gat_agg<4, 128, 32><<<(Nn * 32 + TB - 1) / TB, TB>>>(h1, sv, dv, b1, rp, esrc, o1, Nn);
    }
    // ---- layer 2: 512 -> 4x32 ----
    {
        dim3 g(128 / 128, (Nn + 127) / 128);
        sgemm_nt_big<<<g, 256>>>(o1, W2, h2, Nn, 128, 512);
        k_sd_w<4, 32><<<(Nn * 4 * 32 + TB - 1) / TB, TB>>>(h2, a2s, a2d, sv, dv, Nn);
        gat_agg<4, 32, 32><<<(Nn * 32 + TB - 1) / TB, TB>>>(h2, sv, dv, b2, rp, esrc, o2, Nn);
    }
    // ---- layer 3: 128 -> 1x8 ----
    {
        gemm_thin8<<<(Nn * 8 + 255) / 256, 256>>>(o2, W3, h3, Nn);
        k_sd_w<1, 8><<<(Nn * 32 + TB - 1) / TB, TB>>>(h3, a3s, a3d, sv, dv, Nn);
        gat_agg<1, 8, 8><<<(Nn * 8 + TB - 1) / TB, TB>>>(h3, sv, dv, b3, rp, esrc, o3, Nn);
    }
    // ---- edge MLP ----
    edge_mlp<<<(E + TB - 1) / TB, TB>>>(o3, ei, ea, yr, qt, f1w, f1b, f2w, f2b, out, E);
}

// round 6
// speedup vs baseline: 1.9583x; 1.4077x over previous
#include <cuda_runtime.h>
#include <math.h>

#define NMAX 50000
#define EMAX 400000

// ---------------- scratch (device globals; no dynamic allocation) ----------------
__device__ float g_h1[(size_t)NMAX * 512];
__device__ float g_o1[(size_t)NMAX * 512];
__device__ float g_h2[(size_t)NMAX * 128];
__device__ float g_o2[(size_t)NMAX * 128];
__device__ float g_h3[NMAX * 8];
__device__ float g_o3[NMAX * 8];
__device__ float g_s[NMAX * 4];
__device__ float g_d[NMAX * 4];
__device__ int   g_counts[NMAX];
__device__ int   g_rowptr[NMAX + 1];
__device__ int   g_cursor[NMAX];
__device__ int   g_esrc[EMAX + NMAX];

// ---------------- CSR construction ----------------
__global__ void k_init_counts(int* counts, int nn) {
    int i = blockIdx.x * blockDim.x + threadIdx.x;
    if (i < nn) counts[i] = 1;   // self-loop per node
}

__global__ void k_count_edges(const int* __restrict__ ei, int* counts, int E) {
    int i = blockIdx.x * blockDim.x + threadIdx.x;
    if (i < E) atomicAdd(&counts[ei[E + i]], 1);
}

__global__ void k_scan(const int* __restrict__ counts, int* rp, int* cur, int nn) {
    __shared__ int part[1024];
    int tid = threadIdx.x;
    int per = (nn + 1023) >> 10;
    int b = tid * per;
    int e = min(b + per, nn);
    int s = 0;
    for (int i = b; i < e; i++) s += counts[i];
    part[tid] = s;
    __syncthreads();
    if (tid == 0) {
        int run = 0;
        for (int i = 0; i < 1024; i++) { int v = part[i]; part[i] = run; run += v; }
    }
    __syncthreads();
    int run = part[tid];
    for (int i = b; i < e; i++) { rp[i] = run; cur[i] = run; run += counts[i]; }
    if (e == nn) rp[nn] = run;
}

__global__ void k_scatter(const int* __restrict__ ei, int* cur, int* esrc, int E, int nn) {
    int i = blockIdx.x * blockDim.x + threadIdx.x;
    if (i >= E + nn) return;
    int s, dd;
    if (i < E) { s = ei[i]; dd = ei[E + i]; }
    else       { s = i - E; dd = s; }
    int pos = atomicAdd(&cur[dd], 1);
    esrc[pos] = s;
}

// ---------------- TF32 tensor-core GEMM: C[M,N] = A[M,K] @ B[N,K]^T --------------
// Block tile 128x128, 8 warps (2x4), warp tile 64x32, K-chunk 32.
// Requires N % 128 == 0, K % 32 == 0. M arbitrary.
__device__ __forceinline__ float f2tf32(float x) {
    unsigned u;
    asm("cvt.rna.tf32.f32 %0, %1;" : "=r"(u) : "f"(x));
    return __uint_as_float(u);
}

__global__ __launch_bounds__(256) void mma_nt(
    const float* __restrict__ A, const float* __restrict__ B,
    float* __restrict__ C, int M, int N, int K) {
    __shared__ float As[128][36];   // [m][k], pad 36 -> conflict-free frag loads
    __shared__ float Bs[128][36];   // [n][k]
    const int t = threadIdx.x;
    const int lane = t & 31;
    const int wid = t >> 5;
    const int wm = (wid & 1) * 64;   // warp m-offset
    const int wn = (wid >> 1) * 32;  // warp n-offset
    const int group = lane >> 2, tig = lane & 3;
    const int bm = blockIdx.y * 128, bn = blockIdx.x * 128;
    const int lr = t >> 3;           // 0..31
    const int lc = (t & 7) * 4;      // 0,4,...,28

    float c[4][4][4];
#pragma unroll
    for (int i = 0; i < 4; i++)
#pragma unroll
        for (int j = 0; j < 4; j++)
#pragma unroll
            for (int q = 0; q < 4; q++) c[i][j][q] = 0.f;

    for (int kk = 0; kk < K; kk += 32) {
#pragma unroll
        for (int i = 0; i < 4; i++) {
            int m = lr + i * 32;
            int gm = bm + m;
            float4 av = make_float4(0.f, 0.f, 0.f, 0.f);
            if (gm < M) av = *(const float4*)(A + (size_t)gm * K + kk + lc);
            As[m][lc + 0] = f2tf32(av.x); As[m][lc + 1] = f2tf32(av.y);
            As[m][lc + 2] = f2tf32(av.z); As[m][lc + 3] = f2tf32(av.w);
            float4 bv = *(const float4*)(B + (size_t)(bn + m) * K + kk + lc);
            Bs[m][lc + 0] = f2tf32(bv.x); Bs[m][lc + 1] = f2tf32(bv.y);
            Bs[m][lc + 2] = f2tf32(bv.z); Bs[m][lc + 3] = f2tf32(bv.w);
        }
        __syncthreads();
#pragma unroll
        for (int ks = 0; ks < 32; ks += 8) {
            unsigned bf[4][2];
#pragma unroll
            for (int nf = 0; nf < 4; nf++) {
                const float* bp = &Bs[wn + nf * 8 + group][ks + tig];
                bf[nf][0] = __float_as_uint(bp[0]);
                bf[nf][1] = __float_as_uint(bp[4]);
            }
#pragma unroll
            for (int mf = 0; mf < 4; mf++) {
                const float* ap0 = &As[wm + mf * 16 + group][ks + tig];
                const float* ap1 = &As[wm + mf * 16 + group + 8][ks + tig];
                unsigned a0 = __float_as_uint(ap0[0]);
                unsigned a1 = __float_as_uint(ap1[0]);
                unsigned a2 = __float_as_uint(ap0[4]);
                unsigned a3 = __float_as_uint(ap1[4]);
#pragma unroll
                for (int nf = 0; nf < 4; nf++) {
                    asm volatile(
                        "mma.sync.aligned.m16n8k8.row.col.f32.tf32.tf32.f32 "
                        "{%0,%1,%2,%3}, {%4,%5,%6,%7}, {%8,%9}, {%0,%1,%2,%3};"
                        : "+f"(c[mf][nf][0]), "+f"(c[mf][nf][1]),
                          "+f"(c[mf][nf][2]), "+f"(c[mf][nf][3])
                        : "r"(a0), "r"(a1), "r"(a2), "r"(a3),
                          "r"(bf[nf][0]), "r"(bf[nf][1]));
                }
            }
        }
        __syncthreads();
    }
#pragma unroll
    for (int mf = 0; mf < 4; mf++) {
        int m0 = bm + wm + mf * 16 + group;
        int m1 = m0 + 8;
#pragma unroll
        for (int nf = 0; nf < 4; nf++) {
            int n0 = bn + wn + nf * 8 + tig * 2;
            if (m0 < M) *(float2*)(C + (size_t)m0 * N + n0) = make_float2(c[mf][nf][0], c[mf][nf][1]);
            if (m1 < M) *(float2*)(C + (size_t)m1 * N + n0) = make_float2(c[mf][nf][2], c[mf][nf][3]);
        }
    }
}

// ---------------- thin GEMM for layer 3: C[M,8] = A[M,128] @ W3[8,128]^T ----------
__global__ void gemm_thin8(const float* __restrict__ A, const float* __restrict__ B,
                           float* __restrict__ C, int M) {
    __shared__ float sB[8 * 128];
    for (int i = threadIdx.x; i < 8 * 128; i += blockDim.x) sB[i] = B[i];
    __syncthreads();
    int idx = blockIdx.x * blockDim.x + threadIdx.x;
    if (idx >= M * 8) return;
    int n = idx >> 3, j = idx & 7;
    const float* a = A + (size_t)n * 128;
    const float* w = sB + j * 128;
    float s = 0.f;
#pragma unroll
    for (int k = 0; k < 128; k += 4) {
        float4 v = *(const float4*)(a + k);
        s += v.x * w[k] + v.y * w[k + 1] + v.z * w[k + 2] + v.w * w[k + 3];
    }
    C[idx] = s;
}

// ---------------- per-node attention logits s,d: warp per (node,head) -------------
template <int H, int C>
__global__ void k_sd_w(const float* __restrict__ h, const float* __restrict__ as,
                       const float* __restrict__ ad, float* __restrict__ s,
                       float* __restrict__ d, int nn) {
    int w = (blockIdx.x * blockDim.x + threadIdx.x) >> 5;
    int lane = threadIdx.x & 31;
    if (w >= nn * H) return;
    int n = w / H, hh = w % H;
    float ss = 0.f, dd = 0.f;
    if (lane * 4 < C) {
        float4 v = *(const float4*)(h + (size_t)n * (H * C) + hh * C + lane * 4);
        float4 a = *(const float4*)(as + hh * C + lane * 4);
        float4 b = *(const float4*)(ad + hh * C + lane * 4);
        ss = v.x * a.x + v.y * a.y + v.z * a.z + v.w * a.w;
        dd = v.x * b.x + v.y * b.y + v.z * b.z + v.w * b.w;
    }
#pragma unroll
    for (int o = 16; o; o >>= 1) {
        ss += __shfl_xor_sync(0xffffffffu, ss, o);
        dd += __shfl_xor_sync(0xffffffffu, dd, o);
    }
    if (lane == 0) { s[w] = ss; d[w] = dd; }
}

// ---------------- GAT aggregation (atomic-free, CSR by dst) -----------------------
template <int H, int C, int LPN>
__global__ void gat_agg(const float* __restrict__ h, const float* __restrict__ s,
                        const float* __restrict__ dv, const float* __restrict__ bias,
                        const int* __restrict__ rp, const int* __restrict__ esrc,
                        float* __restrict__ out, int nn) {
    constexpr int F = H * C;
    constexpr int VPL = F / LPN;
    constexpr int NPW = 32 / LPN;
    int gwarp = (blockIdx.x * blockDim.x + threadIdx.x) >> 5;
    int lane = threadIdx.x & 31;
    int node = gwarp * NPW + lane / LPN;
    if (node >= nn) return;
    int sub = lane % LPN;
    int myh = (sub * VPL) / C;
    float dval = dv[node * H + myh];
    int beg = rp[node], end = rp[node + 1];

    // pass 1: per-head max
    float m = -1e30f;
    for (int i = beg + (lane & 7); i < end; i += 8) {
        int sc = esrc[i];
        float e = s[sc * H + myh] + dval;
        e = e > 0.f ? e : 0.2f * e;
        m = fmaxf(m, e);
    }
    m = fmaxf(m, __shfl_xor_sync(0xffffffffu, m, 1));
    m = fmaxf(m, __shfl_xor_sync(0xffffffffu, m, 2));
    m = fmaxf(m, __shfl_xor_sync(0xffffffffu, m, 4));

    // pass 2: accumulate
    float acc[VPL];
#pragma unroll
    for (int j = 0; j < VPL; j++) acc[j] = 0.f;
    float den = 0.f;
    for (int i = beg; i < end; i++) {
        int sc = esrc[i];
        float e = s[sc * H + myh] + dval;
        e = e > 0.f ? e : 0.2f * e;
        float w = __expf(e - m);
        den += w;
        if constexpr (VPL % 4 == 0) {
            const float4* hp4 = reinterpret_cast<const float4*>(h + (size_t)sc * F + sub * VPL);
#pragma unroll
            for (int j = 0; j < VPL / 4; j++) {
                float4 v = hp4[j];
                acc[4 * j + 0] += w * v.x;
                acc[4 * j + 1] += w * v.y;
                acc[4 * j + 2] += w * v.z;
                acc[4 * j + 3] += w * v.w;
            }
        } else {
            const float* hp = h + (size_t)sc * F + sub * VPL;
#pragma unroll
            for (int j = 0; j < VPL; j++) acc[j] += w * hp[j];
        }
    }
    float inv = 1.f / den;
#pragma unroll
    for (int j = 0; j < VPL; j++) {
        float v = acc[j] * inv + bias[sub * VPL + j];
        out[(size_t)node * F + sub * VPL + j] = v > 0.f ? v : expm1f(v);
    }
}

// ---------------- final edge MLP: 19 -> 16 -> 1 ----------------
__global__ void edge_mlp(const float* __restrict__ h3, const int* __restrict__ ei,
                         const float* __restrict__ ea, const float* __restrict__ yr,
                         const float* __restrict__ qt, const float* __restrict__ w1,
                         const float* __restrict__ b1, const float* __restrict__ w2,
                         const float* __restrict__ b2, float* __restrict__ out, int E) {
    __shared__ float sw1[16 * 19], sb1[16], sw2[16], sb2;
    for (int i = threadIdx.x; i < 16 * 19; i += blockDim.x) sw1[i] = w1[i];
    if (threadIdx.x < 16) { sb1[threadIdx.x] = b1[threadIdx.x]; sw2[threadIdx.x] = w2[threadIdx.x]; }
    if (threadIdx.x == 0) sb2 = b2[0];
    __syncthreads();
    int e = blockIdx.x * blockDim.x + threadIdx.x;
    if (e >= E) return;
    int si = ei[e], di = ei[E + e];
    float z[19];
#pragma unroll
    for (int j = 0; j < 8; j++) { z[j] = h3[si * 8 + j]; z[8 + j] = h3[di * 8 + j]; }
    z[16] = ea[e];
    z[17] = yr[e];
    z[18] = qt[e];
    float o = sb2;
#pragma unroll
    for (int j = 0; j < 16; j++) {
        float a = sb1[j];
#pragma unroll
        for (int i = 0; i < 19; i++) a += sw1[j * 19 + i] * z[i];
        o += sw2[j] * fmaxf(a, 0.f);
    }
    out[e] = o;
}

// ---------------- host ----------------
static void* sym_addr(const void* symbol) {
    void* p = nullptr;
    cudaGetSymbolAddress(&p, symbol);
    return p;
}

extern "C" void kernel_launch(void* const* d_in, const int* in_sizes, int n_in,
                              void* d_out, int out_size) {
    const float* x    = (const float*)d_in[0];
    const int*   ei   = (const int*)d_in[1];
    const float* ea   = (const float*)d_in[2];
    const float* yr   = (const float*)d_in[3];
    const float* qt   = (const float*)d_in[4];
    const float* W1   = (const float*)d_in[5];
    const float* a1s  = (const float*)d_in[6];
    const float* a1d  = (const float*)d_in[7];
    const float* b1   = (const float*)d_in[8];
    const float* W2   = (const float*)d_in[9];
    const float* a2s  = (const float*)d_in[10];
    const float* a2d  = (const float*)d_in[11];
    const float* b2   = (const float*)d_in[12];
    const float* W3   = (const float*)d_in[13];
    const float* a3s  = (const float*)d_in[14];
    const float* a3d  = (const float*)d_in[15];
    const float* b3   = (const float*)d_in[16];
    const float* f1w  = (const float*)d_in[17];
    const float* f1b  = (const float*)d_in[18];
    const float* f2w  = (const float*)d_in[19];
    const float* f2b  = (const float*)d_in[20];
    float* out = (float*)d_out;

    const int Nn = in_sizes[0] / 128;
    const int E  = in_sizes[1] / 2;

    float* h1 = (float*)sym_addr(g_h1);
    float* o1 = (float*)sym_addr(g_o1);
    float* h2 = (float*)sym_addr(g_h2);
    float* o2 = (float*)sym_addr(g_o2);
    float* h3 = (float*)sym_addr(g_h3);
    float* o3 = (float*)sym_addr(g_o3);
    float* sv = (float*)sym_addr(g_s);
    float* dv = (float*)sym_addr(g_d);
    int* counts = (int*)sym_addr(g_counts);
    int* rp     = (int*)sym_addr(g_rowptr);
    int* cur    = (int*)sym_addr(g_cursor);
    int* esrc   = (int*)sym_addr(g_esrc);

    const int TB = 128;

    // CSR (dst -> incoming src list), self-loops appended
    k_init_counts<<<(Nn + TB - 1) / TB, TB>>>(counts, Nn);
    k_count_edges<<<(E + TB - 1) / TB, TB>>>(ei, counts, E);
    k_scan<<<1, 1024>>>(counts, rp, cur, Nn);
    k_scatter<<<(E + Nn + TB - 1) / TB, TB>>>(ei, cur, esrc, E, Nn);

    // ---- layer 1: 128 -> 4x128 ----
    {
        dim3 g(512 / 128, (Nn + 127) / 128);
        mma_nt<<<g, 256>>>(x, W1, h1, Nn, 512, 128);
        k_sd_w<4, 128><<<(Nn * 4 * 32 + TB - 1) / TB, TB>>>(h1, a1s, a1d, sv, dv, Nn);
        gat_agg<4, 128, 32><<<(Nn * 32 + TB - 1) / TB, TB>>>(h1, sv, dv, b1, rp, esrc, o1, Nn);
    }
    // ---- layer 2: 512 -> 4x32 ----
    {
        dim3 g(128 / 128, (Nn + 127) / 128);
        mma_nt<<<g, 256>>>(o1, W2, h2, Nn, 128, 512);
        k_sd_w<4, 32><<<(Nn * 4 * 32 + TB - 1) / TB, TB>>>(h2, a2s, a2d, sv, dv, Nn);
        gat_agg<4, 32, 32><<<(Nn * 32 + TB - 1) / TB, TB>>>(h2, sv, dv, b2, rp, esrc, o2, Nn);
    }
    // ---- layer 3: 128 -> 1x8 ----
    {
        gemm_thin8<<<(Nn * 8 + 255) / 256, 256>>>(o2, W3, h3, Nn);
        k_sd_w<1, 8><<<(Nn * 32 + TB - 1) / TB, TB>>>(h3, a3s, a3d, sv, dv, Nn);
        gat_agg<1, 8, 8><<<(Nn * 8 + TB - 1) / TB, TB>>>(h3, sv, dv, b3, rp, esrc, o3, Nn);
    }
    // ---- edge MLP ----
    edge_mlp<<<(E + TB - 1) / TB, TB>>>(o3, ei, ea, yr, qt, f1w, f1b, f2w, f2b, out, E);
}